// round 6
// baseline (speedup 1.0000x reference)
#include <cuda_runtime.h>
#include <utility>
#include <cstddef>

// ============================================================================
// Compile-time Clifford algebra tables for N_GEN = 6 (DIM = 64).
// Blades sorted by (popcount, value); cls = grade % 4.
// For output index j and left index i:  k = index[blade_i ^ blade_j],
// sign = swap parity(blade_i, blade_k), p = path-rank of (cls_i,cls_j,cls_k)
// in row-major order over the realized (4,4,4) path set (matches np.argwhere).
// ============================================================================

struct Alg {
    int blade[64];
    int cls[64];
    signed char ktab[64][64];   // [j][i] -> k
    signed char sgn[64][64];    // [j][i] -> 1 if negative
    signed char ptab[64][64];   // [j][i] -> w_gp column p
    int P;
};

constexpr int popc6(int x) { int c = 0; for (int b = 0; b < 6; ++b) c += (x >> b) & 1; return c; }

constexpr Alg make_alg() {
    Alg a{};
    int idx = 0;
    for (int g = 0; g <= 6; ++g)
        for (int b = 0; b < 64; ++b)
            if (popc6(b) == g) a.blade[idx++] = b;
    int inv[64] = {};
    for (int i = 0; i < 64; ++i) inv[a.blade[i]] = i;
    for (int i = 0; i < 64; ++i) a.cls[i] = popc6(a.blade[i]) & 3;

    bool paths[64] = {};
    for (int i = 0; i < 64; ++i)
        for (int k = 0; k < 64; ++k) {
            int j = inv[a.blade[i] ^ a.blade[k]];
            paths[a.cls[i] * 16 + a.cls[j] * 4 + a.cls[k]] = true;
        }
    int pmap[64] = {};
    int P = 0;
    for (int t = 0; t < 64; ++t) pmap[t] = paths[t] ? P++ : -1;
    a.P = P;

    for (int j = 0; j < 64; ++j)
        for (int i = 0; i < 64; ++i) {
            int bi = a.blade[i], bj = a.blade[j];
            int bk = bi ^ bj;
            int k = inv[bk];
            a.ktab[j][i] = (signed char)k;
            int s = 0;
            int t = bi >> 1;
            while (t) { s += popc6(t & bk); t >>= 1; }
            a.sgn[j][i] = (signed char)(s & 1);
            a.ptab[j][i] = (signed char)pmap[a.cls[i] * 16 + a.cls[j] * 4 + a.cls[k]];
        }
    return a;
}

constexpr Alg ALG = make_alg();
constexpr int PN = ALG.P;   // number of realized class paths (columns of w_gp)

// ---- Scalar constexpr wrappers: device code only sees folded integers. ----
// (Direct member access like ALG.ktab[J][I] in device code odr-uses the host
//  constexpr struct and fails to compile; static constexpr int members do not.)
template <int J, int I> struct GT {
    static constexpr int  k   = (int)ALG.ktab[J][I];
    static constexpr int  p   = (int)ALG.ptab[J][I];
    static constexpr bool neg = ALG.sgn[J][I] != 0;
};
template <int I> struct CT {
    static constexpr int c = ALG.cls[I];
};

static constexpr int NB = 256;   // batch
static constexpr int NF = 128;   // features
static constexpr int DV = 64;    // DIM

// ---------------------------------------------------------------------------
// Template helpers (all table indices are compile-time constants -> registers)
// ---------------------------------------------------------------------------

template <int C>
__device__ __forceinline__ float pick(const float4& w) {
    if constexpr (C == 0) return w.x;
    else if constexpr (C == 1) return w.y;
    else if constexpr (C == 2) return w.z;
    else return w.w;
}

template <int T>
__device__ __forceinline__ void lin_chunk(float* acc, const float4& w4, const float4 xc) {
    acc[4 * T + 0] = fmaf(xc.x, pick<CT<4 * T + 0>::c>(w4), acc[4 * T + 0]);
    acc[4 * T + 1] = fmaf(xc.y, pick<CT<4 * T + 1>::c>(w4), acc[4 * T + 1]);
    acc[4 * T + 2] = fmaf(xc.z, pick<CT<4 * T + 2>::c>(w4), acc[4 * T + 2]);
    acc[4 * T + 3] = fmaf(xc.w, pick<CT<4 * T + 3>::c>(w4), acc[4 * T + 3]);
}

template <std::size_t... Ts>
__device__ __forceinline__ void lin_m(float* acc, const float4& w4, const float4* xm4,
                                      std::index_sequence<Ts...>) {
    (lin_chunk<(int)Ts>(acc, w4, xm4[Ts]), ...);
}

template <std::size_t... Is>
__device__ __forceinline__ void sq_accum(float* sq, const float* acc, std::index_sequence<Is...>) {
    ((sq[CT<(int)Is>::c] = fmaf(acc[Is], acc[Is], sq[CT<(int)Is>::c])), ...);
}

template <std::size_t... Is>
__device__ __forceinline__ void xr_scale(float* xr, const float* acc, const float* inv,
                                         std::index_sequence<Is...>) {
    ((xr[Is] = acc[Is] * inv[CT<(int)Is>::c]), ...);
}

template <std::size_t... Ps>
__device__ __forceinline__ void load_w(float* w, const float* __restrict__ wg,
                                       std::index_sequence<Ps...>) {
    ((w[Ps] = wg[Ps]), ...);
}

// One output row j: acc_j = sum_i (+/-) w[p(j,i)] * x[i] * xr[k(j,i)]
template <int J, std::size_t... Is>
__device__ __forceinline__ float gp_row(const float* xv, const float* xr, const float* w,
                                        std::index_sequence<Is...>) {
    float acc = 0.f;
    ((acc = fmaf(xv[Is] * xr[GT<J, (int)Is>::k],
                 (GT<J, (int)Is>::neg ? -w[GT<J, (int)Is>::p] : w[GT<J, (int)Is>::p]),
                 acc)),
     ...);
    return acc;
}

template <int G>
__device__ __forceinline__ void gp_group(float* __restrict__ op, const float* xv,
                                         const float* xr, const float* w) {
    float4 v;
    v.x = gp_row<4 * G + 0>(xv, xr, w, std::make_index_sequence<64>{});
    v.y = gp_row<4 * G + 1>(xv, xr, w, std::make_index_sequence<64>{});
    v.z = gp_row<4 * G + 2>(xv, xr, w, std::make_index_sequence<64>{});
    v.w = gp_row<4 * G + 3>(xv, xr, w, std::make_index_sequence<64>{});
    reinterpret_cast<float4*>(op)[G] = v;
}

template <std::size_t... Gs>
__device__ __forceinline__ void gp_all(float* __restrict__ op, const float* xv, const float* xr,
                                       const float* w, std::index_sequence<Gs...>) {
    (gp_group<(int)Gs>(op, xv, xr, w), ...);
}

// ---------------------------------------------------------------------------
// Kernel: one CTA per batch element b, one thread per feature n.
// ---------------------------------------------------------------------------

__global__ void __launch_bounds__(128, 2)
qgp_kernel(const float* __restrict__ x, const float* __restrict__ w_gp,
           const float* __restrict__ w_lin, const float* __restrict__ b_lin,
           const float* __restrict__ a_norm, float* __restrict__ out) {
    __shared__ float x_s[NF * DV];   // x[b, m, i], 32 KB

    const int b = blockIdx.x;
    const int n = threadIdx.x;

    // Stage x[b] into smem (coalesced float4).
    {
        const float4* xg = reinterpret_cast<const float4*>(x + (size_t)b * NF * DV);
        float4* xs4 = reinterpret_cast<float4*>(x_s);
#pragma unroll
        for (int t = 0; t < 16; ++t) xs4[t * 128 + n] = xg[t * 128 + n];
    }
    __syncthreads();

    // ---- Linear phase: xr[n,i] = sum_m x[b,m,i] * w_lin[n,m,cls[i]] ----
    float acc[DV];
#pragma unroll
    for (int i = 0; i < DV; ++i) acc[i] = 0.f;

    const float4* wl = reinterpret_cast<const float4*>(w_lin + (size_t)n * NF * 4);
#pragma unroll 2
    for (int m = 0; m < NF; ++m) {
        const float4 w4 = wl[m];
        const float4* xm4 = reinterpret_cast<const float4*>(x_s + m * DV);
        lin_m(acc, w4, xm4, std::make_index_sequence<16>{});
    }
    acc[0] += b_lin[n];

    // ---- Norms per class, sigmoid gate, scale ----
    float sq[4] = {0.f, 0.f, 0.f, 0.f};
    sq_accum(sq, acc, std::make_index_sequence<64>{});

    float inv[4];
#pragma unroll
    for (int c = 0; c < 4; ++c) {
        float nrm = sqrtf(sq[c]);
        float an = a_norm[n * 4 + c];
        float sig = 1.f / (1.f + expf(-an));
        float gate = fmaf(sig, nrm - 1.f, 1.f);
        inv[c] = 1.f / (gate + 1e-6f);
    }

    float xr[DV];
    xr_scale(xr, acc, inv, std::make_index_sequence<64>{});

    // ---- Load x[b,n,:] and w_gp[n,:] into registers ----
    float xv[DV];
    {
        const float4* xn = reinterpret_cast<const float4*>(x + ((size_t)b * NF + n) * DV);
#pragma unroll
        for (int t = 0; t < 16; ++t) {
            float4 v = xn[t];
            xv[4 * t + 0] = v.x;
            xv[4 * t + 1] = v.y;
            xv[4 * t + 2] = v.z;
            xv[4 * t + 3] = v.w;
        }
    }

    float w[PN];
    load_w(w, w_gp + (size_t)n * PN, std::make_index_sequence<PN>{});

    // ---- Geometric product: fully unrolled, all-register ----
    float* op = out + ((size_t)b * NF + n) * DV;
    gp_all(op, xv, xr, w, std::make_index_sequence<16>{});
}

// ---------------------------------------------------------------------------

extern "C" void kernel_launch(void* const* d_in, const int* in_sizes, int n_in,
                              void* d_out, int out_size) {
    (void)in_sizes; (void)n_in; (void)out_size;
    const float* x      = (const float*)d_in[0];
    const float* w_gp   = (const float*)d_in[1];
    const float* w_lin  = (const float*)d_in[2];
    const float* b_lin  = (const float*)d_in[3];
    const float* a_norm = (const float*)d_in[4];
    float* out = (float*)d_out;

    qgp_kernel<<<NB, NF>>>(x, w_gp, w_lin, b_lin, a_norm, out);
}

// round 7
// speedup vs baseline: 1.0488x; 1.0488x over previous
#include <cuda_runtime.h>
#include <utility>
#include <cstddef>

// ============================================================================
// Compile-time Clifford algebra tables for N_GEN = 6 (DIM = 64).
// ============================================================================

struct Alg {
    int blade[64];
    int cls[64];
    signed char ktab[64][64];   // [j][i] -> k
    signed char sgn[64][64];    // [j][i] -> 1 if negative
    signed char ptab[64][64];   // [j][i] -> w_gp column p
    int P;
};

constexpr int popc6(int x) { int c = 0; for (int b = 0; b < 6; ++b) c += (x >> b) & 1; return c; }

constexpr Alg make_alg() {
    Alg a{};
    int idx = 0;
    for (int g = 0; g <= 6; ++g)
        for (int b = 0; b < 64; ++b)
            if (popc6(b) == g) a.blade[idx++] = b;
    int inv[64] = {};
    for (int i = 0; i < 64; ++i) inv[a.blade[i]] = i;
    for (int i = 0; i < 64; ++i) a.cls[i] = popc6(a.blade[i]) & 3;

    bool paths[64] = {};
    for (int i = 0; i < 64; ++i)
        for (int k = 0; k < 64; ++k) {
            int j = inv[a.blade[i] ^ a.blade[k]];
            paths[a.cls[i] * 16 + a.cls[j] * 4 + a.cls[k]] = true;
        }
    int pmap[64] = {};
    int P = 0;
    for (int t = 0; t < 64; ++t) pmap[t] = paths[t] ? P++ : -1;
    a.P = P;

    for (int j = 0; j < 64; ++j)
        for (int i = 0; i < 64; ++i) {
            int bi = a.blade[i], bj = a.blade[j];
            int bk = bi ^ bj;
            int k = inv[bk];
            a.ktab[j][i] = (signed char)k;
            int s = 0;
            int t = bi >> 1;
            while (t) { s += popc6(t & bk); t >>= 1; }
            a.sgn[j][i] = (signed char)(s & 1);
            a.ptab[j][i] = (signed char)pmap[a.cls[i] * 16 + a.cls[j] * 4 + a.cls[k]];
        }
    return a;
}

constexpr Alg ALG = make_alg();
constexpr int PN = ALG.P;

// ---- Scalar constexpr wrappers: device code must only see folded integers.
template <int J, int I> struct GT {
    static constexpr int  k   = (int)ALG.ktab[J][I];
    static constexpr int  p   = (int)ALG.ptab[J][I];
    static constexpr bool neg = ALG.sgn[J][I] != 0;
};
template <int I> struct CT {
    static constexpr int c = ALG.cls[I];
};
// Class pattern of adjacent index pair (2Q, 2Q+1).
template <int Q> struct PP {
    static constexpr int cl = ALG.cls[2 * Q];
    static constexpr int ch = ALG.cls[2 * Q + 1];
};

// Verify all 32 adjacent pairs fall in the 6 supported patterns.
constexpr bool pat_ok() {
    for (int q = 0; q < 32; ++q) {
        int cl = ALG.cls[2 * q], ch = ALG.cls[2 * q + 1];
        bool ok = (cl == 0 && ch == 0) || (cl == 0 && ch == 1) || (cl == 1 && ch == 1) ||
                  (cl == 1 && ch == 2) || (cl == 2 && ch == 2) || (cl == 3 && ch == 3);
        if (!ok) return false;
    }
    return true;
}
static_assert(pat_ok(), "unexpected adjacent class pattern");

static constexpr int NB = 256;   // batch
static constexpr int NF = 128;   // features
static constexpr int DV = 64;    // DIM

// ---------------------------------------------------------------------------
// Packed f32x2 helpers
// ---------------------------------------------------------------------------

using u64 = unsigned long long;

__device__ __forceinline__ u64 fma2(u64 a, u64 b, u64 c) {
    u64 d;
    asm("fma.rn.f32x2 %0, %1, %2, %3;" : "=l"(d) : "l"(a), "l"(b), "l"(c));
    return d;
}

// wp order: [0]=(0,0) [1]=(0,1) [2]=(1,1) [3]=(1,2) [4]=(2,2) [5]=(3,3)
template <int CL, int CH>
__device__ __forceinline__ u64 selw(const u64* wp) {
    if constexpr (CL == 0 && CH == 0) return wp[0];
    else if constexpr (CL == 0 && CH == 1) return wp[1];
    else if constexpr (CL == 1 && CH == 1) return wp[2];
    else if constexpr (CL == 1 && CH == 2) return wp[3];
    else if constexpr (CL == 2 && CH == 2) return wp[4];
    else return wp[5];  // (3,3)
}

// One m-step of the linear phase: 16 LDS.128 (as ulonglong2) + 32 FFMA2.
template <std::size_t... Ts>
__device__ __forceinline__ void lin_m2(u64* acc2, const u64* wp, const ulonglong2* xm,
                                       std::index_sequence<Ts...>) {
    ([&] {
        const ulonglong2 v = xm[Ts];
        acc2[2 * Ts]     = fma2(v.x, selw<PP<2 * (int)Ts>::cl,     PP<2 * (int)Ts>::ch>(wp),
                                acc2[2 * Ts]);
        acc2[2 * Ts + 1] = fma2(v.y, selw<PP<2 * (int)Ts + 1>::cl, PP<2 * (int)Ts + 1>::ch>(wp),
                                acc2[2 * Ts + 1]);
    }(), ...);
}

// ---------------------------------------------------------------------------
// GP-phase template helpers (unchanged from the passing kernel)
// ---------------------------------------------------------------------------

template <std::size_t... Is>
__device__ __forceinline__ void sq_accum(float* sq, const float* acc, std::index_sequence<Is...>) {
    ((sq[CT<(int)Is>::c] = fmaf(acc[Is], acc[Is], sq[CT<(int)Is>::c])), ...);
}

template <std::size_t... Is>
__device__ __forceinline__ void xr_scale(float* xr, const float* acc, const float* inv,
                                         std::index_sequence<Is...>) {
    ((xr[Is] = acc[Is] * inv[CT<(int)Is>::c]), ...);
}

template <std::size_t... Ps>
__device__ __forceinline__ void load_w(float* w, const float* __restrict__ wg,
                                       std::index_sequence<Ps...>) {
    ((w[Ps] = wg[Ps]), ...);
}

template <int J, std::size_t... Is>
__device__ __forceinline__ float gp_row(const float* xv, const float* xr, const float* w,
                                        std::index_sequence<Is...>) {
    float acc = 0.f;
    ((acc = fmaf(xv[Is] * xr[GT<J, (int)Is>::k],
                 (GT<J, (int)Is>::neg ? -w[GT<J, (int)Is>::p] : w[GT<J, (int)Is>::p]),
                 acc)),
     ...);
    return acc;
}

template <int G>
__device__ __forceinline__ void gp_group(float* __restrict__ op, const float* xv,
                                         const float* xr, const float* w) {
    float4 v;
    v.x = gp_row<4 * G + 0>(xv, xr, w, std::make_index_sequence<64>{});
    v.y = gp_row<4 * G + 1>(xv, xr, w, std::make_index_sequence<64>{});
    v.z = gp_row<4 * G + 2>(xv, xr, w, std::make_index_sequence<64>{});
    v.w = gp_row<4 * G + 3>(xv, xr, w, std::make_index_sequence<64>{});
    reinterpret_cast<float4*>(op)[G] = v;
}

template <std::size_t... Gs>
__device__ __forceinline__ void gp_all(float* __restrict__ op, const float* xv, const float* xr,
                                       const float* w, std::index_sequence<Gs...>) {
    (gp_group<(int)Gs>(op, xv, xr, w), ...);
}

// ---------------------------------------------------------------------------
// Transposed w_lin scratch: [m][n] float4 (coalesced across lanes n).
// ---------------------------------------------------------------------------

__device__ float4 g_wlt[NF * NF];

__global__ void wlt_kernel(const float4* __restrict__ w) {
    int idx = blockIdx.x * 256 + threadIdx.x;   // 16384 float4 elements
    int n = idx >> 7;
    int m = idx & 127;
    g_wlt[m * NF + n] = w[idx];   // read coalesced (w is [n][m]), write strided (one-time)
}

// ---------------------------------------------------------------------------
// Main kernel: one CTA per batch element b, one thread per feature n.
// ---------------------------------------------------------------------------

__global__ void __launch_bounds__(128, 2)
qgp_kernel(const float* __restrict__ x, const float* __restrict__ w_gp,
           const float* __restrict__ b_lin, const float* __restrict__ a_norm,
           float* __restrict__ out) {
    __shared__ __align__(16) float x_s[NF * DV];   // x[b, m, i], 32 KB

    const int b = blockIdx.x;
    const int n = threadIdx.x;

    // Stage x[b] into smem (coalesced float4).
    {
        const float4* xg = reinterpret_cast<const float4*>(x + (size_t)b * NF * DV);
        float4* xs4 = reinterpret_cast<float4*>(x_s);
#pragma unroll
        for (int t = 0; t < 16; ++t) xs4[t * 128 + n] = xg[t * 128 + n];
    }
    __syncthreads();

    // ---- Linear phase (packed f32x2): xr[n,i] = sum_m x[b,m,i] * w_lin[n,m,cls[i]] ----
    u64 acc2[32];
#pragma unroll
    for (int q = 0; q < 32; ++q) acc2[q] = 0ull;

#pragma unroll 4
    for (int m = 0; m < NF; ++m) {
        const float4 w4 = g_wlt[m * NF + n];   // coalesced across lanes
        u64 wp[6];
        asm("mov.b64 %0, {%1,%1};" : "=l"(wp[0]) : "f"(w4.x));
        asm("mov.b64 %0, {%1,%2};" : "=l"(wp[1]) : "f"(w4.x), "f"(w4.y));
        asm("mov.b64 %0, {%1,%1};" : "=l"(wp[2]) : "f"(w4.y));
        asm("mov.b64 %0, {%1,%2};" : "=l"(wp[3]) : "f"(w4.y), "f"(w4.z));
        asm("mov.b64 %0, {%1,%1};" : "=l"(wp[4]) : "f"(w4.z));
        asm("mov.b64 %0, {%1,%1};" : "=l"(wp[5]) : "f"(w4.w));
        const ulonglong2* xm = reinterpret_cast<const ulonglong2*>(x_s + m * DV);
        lin_m2(acc2, wp, xm, std::make_index_sequence<16>{});
    }

    // Unpack packed accumulators to scalars.
    float acc[DV];
#pragma unroll
    for (int q = 0; q < 32; ++q)
        asm("mov.b64 {%0,%1}, %2;" : "=f"(acc[2 * q]), "=f"(acc[2 * q + 1]) : "l"(acc2[q]));

    acc[0] += b_lin[n];

    // ---- Norms per class, sigmoid gate, scale ----
    float sq[4] = {0.f, 0.f, 0.f, 0.f};
    sq_accum(sq, acc, std::make_index_sequence<64>{});

    float inv[4];
#pragma unroll
    for (int c = 0; c < 4; ++c) {
        float nrm = sqrtf(sq[c]);
        float an = a_norm[n * 4 + c];
        float sig = 1.f / (1.f + expf(-an));
        float gate = fmaf(sig, nrm - 1.f, 1.f);
        inv[c] = 1.f / (gate + 1e-6f);
    }

    float xr[DV];
    xr_scale(xr, acc, inv, std::make_index_sequence<64>{});

    // ---- Load x[b,n,:] and w_gp[n,:] into registers ----
    float xv[DV];
    {
        const float4* xn = reinterpret_cast<const float4*>(x + ((size_t)b * NF + n) * DV);
#pragma unroll
        for (int t = 0; t < 16; ++t) {
            float4 v = xn[t];
            xv[4 * t + 0] = v.x;
            xv[4 * t + 1] = v.y;
            xv[4 * t + 2] = v.z;
            xv[4 * t + 3] = v.w;
        }
    }

    float w[PN];
    load_w(w, w_gp + (size_t)n * PN, std::make_index_sequence<PN>{});

    // ---- Geometric product: fully unrolled, all-register ----
    float* op = out + ((size_t)b * NF + n) * DV;
    gp_all(op, xv, xr, w, std::make_index_sequence<16>{});
}

// ---------------------------------------------------------------------------

extern "C" void kernel_launch(void* const* d_in, const int* in_sizes, int n_in,
                              void* d_out, int out_size) {
    (void)in_sizes; (void)n_in; (void)out_size;
    const float* x      = (const float*)d_in[0];
    const float* w_gp   = (const float*)d_in[1];
    const float* w_lin  = (const float*)d_in[2];
    const float* b_lin  = (const float*)d_in[3];
    const float* a_norm = (const float*)d_in[4];
    float* out = (float*)d_out;

    wlt_kernel<<<64, 256>>>((const float4*)w_lin);
    qgp_kernel<<<NB, NF>>>(x, w_gp, b_lin, a_norm, out);
}

// round 8
// speedup vs baseline: 1.6739x; 1.5960x over previous
#include <cuda_runtime.h>
#include <utility>
#include <cstddef>

// ============================================================================
// Compile-time Clifford algebra tables for N_GEN = 6 (DIM = 64).
// ============================================================================

struct Alg {
    int blade[64];
    int cls[64];
    signed char ktab[64][64];   // [j][i] -> k
    signed char sgn[64][64];    // [j][i] -> 1 if negative
    signed char ptab[64][64];   // [j][i] -> w_gp column p
    int P;
};

constexpr int popc6(int x) { int c = 0; for (int b = 0; b < 6; ++b) c += (x >> b) & 1; return c; }

constexpr Alg make_alg() {
    Alg a{};
    int idx = 0;
    for (int g = 0; g <= 6; ++g)
        for (int b = 0; b < 64; ++b)
            if (popc6(b) == g) a.blade[idx++] = b;
    int inv[64] = {};
    for (int i = 0; i < 64; ++i) inv[a.blade[i]] = i;
    for (int i = 0; i < 64; ++i) a.cls[i] = popc6(a.blade[i]) & 3;

    bool paths[64] = {};
    for (int i = 0; i < 64; ++i)
        for (int k = 0; k < 64; ++k) {
            int j = inv[a.blade[i] ^ a.blade[k]];
            paths[a.cls[i] * 16 + a.cls[j] * 4 + a.cls[k]] = true;
        }
    int pmap[64] = {};
    int P = 0;
    for (int t = 0; t < 64; ++t) pmap[t] = paths[t] ? P++ : -1;
    a.P = P;

    for (int j = 0; j < 64; ++j)
        for (int i = 0; i < 64; ++i) {
            int bi = a.blade[i], bj = a.blade[j];
            int bk = bi ^ bj;
            int k = inv[bk];
            a.ktab[j][i] = (signed char)k;
            int s = 0;
            int t = bi >> 1;
            while (t) { s += popc6(t & bk); t >>= 1; }
            a.sgn[j][i] = (signed char)(s & 1);
            a.ptab[j][i] = (signed char)pmap[a.cls[i] * 16 + a.cls[j] * 4 + a.cls[k]];
        }
    return a;
}

constexpr Alg ALG = make_alg();
constexpr int PN = ALG.P;

// ---- Per-row slot plan: group the 64 terms of output row j by w_gp column p.
struct RowPlan {
    signed char slot[64];   // term i -> local accumulator slot
    signed char pofs[8];    // slot -> p
    signed char first[64];  // 1 if term i is the first hit of its slot
    int ns;
};

constexpr RowPlan make_plan(int j) {
    RowPlan r{};
    r.ns = 0;
    for (int s = 0; s < 8; ++s) r.pofs[s] = -1;
    for (int i = 0; i < 64; ++i) {
        int p = ALG.ptab[j][i];
        int s = 0;
        for (; s < r.ns; ++s)
            if (r.pofs[s] == p) break;
        r.first[i] = (s == r.ns) ? 1 : 0;
        if (s == r.ns) r.pofs[r.ns++] = (signed char)p;
        r.slot[i] = (signed char)s;
    }
    return r;
}

constexpr bool ns_ok() {
    for (int j = 0; j < 64; ++j)
        if (make_plan(j).ns > 8) return false;
    return true;
}
static_assert(ns_ok(), "row uses more than 8 distinct paths");

// ---- Scalar constexpr wrappers: device code must only see folded integers.
template <int J, int I> struct GT {
    static constexpr int  k   = (int)ALG.ktab[J][I];
    static constexpr bool neg = ALG.sgn[J][I] != 0;
    static constexpr int  s   = (int)make_plan(J).slot[I];
    static constexpr bool fst = make_plan(J).first[I] != 0;
};
template <int J, int S> struct SP {
    static constexpr int p = (int)make_plan(J).pofs[S];
};
template <int J> struct RN {
    static constexpr int ns = make_plan(J).ns;
};
template <int I> struct CT {
    static constexpr int c = ALG.cls[I];
};
template <int Q> struct PP {
    static constexpr int cl = ALG.cls[2 * Q];
    static constexpr int ch = ALG.cls[2 * Q + 1];
};

constexpr bool pat_ok() {
    for (int q = 0; q < 32; ++q) {
        int cl = ALG.cls[2 * q], ch = ALG.cls[2 * q + 1];
        bool ok = (cl == 0 && ch == 0) || (cl == 0 && ch == 1) || (cl == 1 && ch == 1) ||
                  (cl == 1 && ch == 2) || (cl == 2 && ch == 2) || (cl == 3 && ch == 3);
        if (!ok) return false;
    }
    return true;
}
static_assert(pat_ok(), "unexpected adjacent class pattern");

static constexpr int NB  = 256;   // batch
static constexpr int NF  = 128;   // features
static constexpr int DV  = 64;    // DIM
static constexpr int XS  = 68;    // padded smem stride (floats), 16B-aligned, kills LDS conflicts

// ---------------------------------------------------------------------------
// Packed f32x2 helpers (linear phase)
// ---------------------------------------------------------------------------

using u64 = unsigned long long;

__device__ __forceinline__ u64 fma2(u64 a, u64 b, u64 c) {
    u64 d;
    asm("fma.rn.f32x2 %0, %1, %2, %3;" : "=l"(d) : "l"(a), "l"(b), "l"(c));
    return d;
}

// wp order: [0]=(0,0) [1]=(0,1) [2]=(1,1) [3]=(1,2) [4]=(2,2) [5]=(3,3)
template <int CL, int CH>
__device__ __forceinline__ u64 selw(const u64* wp) {
    if constexpr (CL == 0 && CH == 0) return wp[0];
    else if constexpr (CL == 0 && CH == 1) return wp[1];
    else if constexpr (CL == 1 && CH == 1) return wp[2];
    else if constexpr (CL == 1 && CH == 2) return wp[3];
    else if constexpr (CL == 2 && CH == 2) return wp[4];
    else return wp[5];  // (3,3)
}

template <std::size_t... Ts>
__device__ __forceinline__ void lin_m2(u64* acc2, const u64* wp, const ulonglong2* xm,
                                       std::index_sequence<Ts...>) {
    ([&] {
        const ulonglong2 v = xm[Ts];
        acc2[2 * Ts]     = fma2(v.x, selw<PP<2 * (int)Ts>::cl,     PP<2 * (int)Ts>::ch>(wp),
                                acc2[2 * Ts]);
        acc2[2 * Ts + 1] = fma2(v.y, selw<PP<2 * (int)Ts + 1>::cl, PP<2 * (int)Ts + 1>::ch>(wp),
                                acc2[2 * Ts + 1]);
    }(), ...);
}

// ---------------------------------------------------------------------------
// Misc template helpers
// ---------------------------------------------------------------------------

template <std::size_t... Is>
__device__ __forceinline__ void sq_accum(float* sq, const float* acc, std::index_sequence<Is...>) {
    ((sq[CT<(int)Is>::c] = fmaf(acc[Is], acc[Is], sq[CT<(int)Is>::c])), ...);
}

template <std::size_t... Is>
__device__ __forceinline__ void xr_scale(float* xr, const float* acc, const float* inv,
                                         std::index_sequence<Is...>) {
    ((xr[Is] = acc[Is] * inv[CT<(int)Is>::c]), ...);
}

template <std::size_t... Ps>
__device__ __forceinline__ void load_w(float* w, const float* __restrict__ wg,
                                       std::index_sequence<Ps...>) {
    ((w[Ps] = wg[Ps]), ...);
}

// ---------------------------------------------------------------------------
// GP phase: sign-folded slot accumulation (1 FFMA per term).
//   S_{slot} += x_i * (+/- xr_k);  out_j = sum_slots w[p(slot)] * S_slot
// ---------------------------------------------------------------------------

template <int J, int I>
__device__ __forceinline__ void gp_term(float* S, const float* xv, const float* xr) {
    const float xrk = GT<J, I>::neg ? -xr[GT<J, I>::k] : xr[GT<J, I>::k];
    if constexpr (GT<J, I>::fst)
        S[GT<J, I>::s] = xv[I] * xrk;
    else
        S[GT<J, I>::s] = fmaf(xv[I], xrk, S[GT<J, I>::s]);
}

template <int J, int S8>
__device__ __forceinline__ void gp_comb(float& acc, const float* S, const float* w) {
    if constexpr (S8 < RN<J>::ns) acc = fmaf(w[SP<J, S8>::p], S[S8], acc);
}

template <int J, std::size_t... Is>
__device__ __forceinline__ float gp_row(const float* xv, const float* xr, const float* w,
                                        std::index_sequence<Is...>) {
    float S[8];
    (gp_term<J, (int)Is>(S, xv, xr), ...);
    float acc = 0.f;
    gp_comb<J, 0>(acc, S, w); gp_comb<J, 1>(acc, S, w);
    gp_comb<J, 2>(acc, S, w); gp_comb<J, 3>(acc, S, w);
    gp_comb<J, 4>(acc, S, w); gp_comb<J, 5>(acc, S, w);
    gp_comb<J, 6>(acc, S, w); gp_comb<J, 7>(acc, S, w);
    return acc;
}

template <int G>
__device__ __forceinline__ void gp_group(float* __restrict__ op, const float* xv,
                                         const float* xr, const float* w) {
    float4 v;
    v.x = gp_row<4 * G + 0>(xv, xr, w, std::make_index_sequence<64>{});
    v.y = gp_row<4 * G + 1>(xv, xr, w, std::make_index_sequence<64>{});
    v.z = gp_row<4 * G + 2>(xv, xr, w, std::make_index_sequence<64>{});
    v.w = gp_row<4 * G + 3>(xv, xr, w, std::make_index_sequence<64>{});
    reinterpret_cast<float4*>(op)[G] = v;
}

template <std::size_t... Gs>
__device__ __forceinline__ void gp_all(float* __restrict__ op, const float* xv, const float* xr,
                                       const float* w, std::index_sequence<Gs...>) {
    (gp_group<(int)Gs>(op, xv, xr, w), ...);
}

// ---------------------------------------------------------------------------
// Transposed w_lin scratch: [m][n] float4 (coalesced across lanes n).
// ---------------------------------------------------------------------------

__device__ float4 g_wlt[NF * NF];

__global__ void wlt_kernel(const float4* __restrict__ w) {
    int idx = blockIdx.x * 256 + threadIdx.x;   // 16384 float4 elements
    int n = idx >> 7;
    int m = idx & 127;
    g_wlt[m * NF + n] = w[idx];
}

// ---------------------------------------------------------------------------
// Main kernel: one CTA per batch element b, one thread per feature n.
// ---------------------------------------------------------------------------

__global__ void __launch_bounds__(128, 2)
qgp_kernel(const float* __restrict__ x, const float* __restrict__ w_gp,
           const float* __restrict__ b_lin, const float* __restrict__ a_norm,
           float* __restrict__ out) {
    __shared__ __align__(16) float x_s[NF * XS];   // x[b, m, i] padded to stride 68

    const int b = blockIdx.x;
    const int n = threadIdx.x;

    // Stage x[b] into smem (coalesced gmem reads, padded smem rows).
    {
        const float4* xg = reinterpret_cast<const float4*>(x + (size_t)b * NF * DV);
#pragma unroll
        for (int t = 0; t < 16; ++t) {
            int idx = t * 128 + n;
            int m = idx >> 4, c = idx & 15;
            *reinterpret_cast<float4*>(x_s + m * XS + c * 4) = xg[idx];
        }
    }
    __syncthreads();

    // ---- Linear phase (packed f32x2): xr[n,i] = sum_m x[b,m,i] * w_lin[n,m,cls[i]] ----
    u64 acc2[32];
#pragma unroll
    for (int q = 0; q < 32; ++q) acc2[q] = 0ull;

#pragma unroll 4
    for (int m = 0; m < NF; ++m) {
        const float4 w4 = g_wlt[m * NF + n];   // coalesced across lanes
        u64 wp[6];
        asm("mov.b64 %0, {%1,%1};" : "=l"(wp[0]) : "f"(w4.x));
        asm("mov.b64 %0, {%1,%2};" : "=l"(wp[1]) : "f"(w4.x), "f"(w4.y));
        asm("mov.b64 %0, {%1,%1};" : "=l"(wp[2]) : "f"(w4.y));
        asm("mov.b64 %0, {%1,%2};" : "=l"(wp[3]) : "f"(w4.y), "f"(w4.z));
        asm("mov.b64 %0, {%1,%1};" : "=l"(wp[4]) : "f"(w4.z));
        asm("mov.b64 %0, {%1,%1};" : "=l"(wp[5]) : "f"(w4.w));
        const ulonglong2* xm = reinterpret_cast<const ulonglong2*>(x_s + m * XS);
        lin_m2(acc2, wp, xm, std::make_index_sequence<16>{});
    }

    float acc[DV];
#pragma unroll
    for (int q = 0; q < 32; ++q)
        asm("mov.b64 {%0,%1}, %2;" : "=f"(acc[2 * q]), "=f"(acc[2 * q + 1]) : "l"(acc2[q]));

    acc[0] += b_lin[n];

    // ---- Norms per class, sigmoid gate, scale ----
    float sq[4] = {0.f, 0.f, 0.f, 0.f};
    sq_accum(sq, acc, std::make_index_sequence<64>{});

    float inv[4];
#pragma unroll
    for (int c = 0; c < 4; ++c) {
        float nrm = sqrtf(sq[c]);
        float an = a_norm[n * 4 + c];
        float sig = 1.f / (1.f + expf(-an));
        float gate = fmaf(sig, nrm - 1.f, 1.f);
        inv[c] = 1.f / (gate + 1e-6f);
    }

    float xr[DV];
    xr_scale(xr, acc, inv, std::make_index_sequence<64>{});

    // ---- xv = x[b,n,:] straight from smem (row m == n), w_gp to registers ----
    float xv[DV];
#pragma unroll
    for (int t = 0; t < 16; ++t) {
        float4 v = *reinterpret_cast<const float4*>(x_s + n * XS + 4 * t);
        xv[4 * t + 0] = v.x;
        xv[4 * t + 1] = v.y;
        xv[4 * t + 2] = v.z;
        xv[4 * t + 3] = v.w;
    }

    float w[PN];
    load_w(w, w_gp + (size_t)n * PN, std::make_index_sequence<PN>{});

    // ---- Geometric product: slot-accumulated, fully unrolled ----
    float* op = out + ((size_t)b * NF + n) * DV;
    gp_all(op, xv, xr, w, std::make_index_sequence<16>{});
}

// ---------------------------------------------------------------------------

extern "C" void kernel_launch(void* const* d_in, const int* in_sizes, int n_in,
                              void* d_out, int out_size) {
    (void)in_sizes; (void)n_in; (void)out_size;
    const float* x      = (const float*)d_in[0];
    const float* w_gp   = (const float*)d_in[1];
    const float* w_lin  = (const float*)d_in[2];
    const float* b_lin  = (const float*)d_in[3];
    const float* a_norm = (const float*)d_in[4];
    float* out = (float*)d_out;

    wlt_kernel<<<64, 256>>>((const float4*)w_lin);
    qgp_kernel<<<NB, NF>>>(x, w_gp, b_lin, a_norm, out);
}